// round 1
// baseline (speedup 1.0000x reference)
#include <cuda_runtime.h>

#define BATCH 4
#define HDIM 384
#define WDIM 384
#define CDIM 64
#define FFDIM 128
#define NPIX (BATCH*HDIM*WDIM)

// Scratch for q,k,v projections (static __device__ arrays: allowed, no runtime alloc)
__device__ float g_q[NPIX*CDIM];
__device__ float g_k[NPIX*CDIM];
__device__ float g_v[NPIX*CDIM];

// ---------------------------------------------------------------------------
// Kernel A: q,k,v = x @ [wq|wk|wv]   (N x 64) @ (64 x 192)
// Block: 64 pixels, 256 threads, register tile 4x12.
// ---------------------------------------------------------------------------
__global__ void __launch_bounds__(256) qkv_kernel(
    const float* __restrict__ x,
    const float* __restrict__ wq,
    const float* __restrict__ wk,
    const float* __restrict__ wv)
{
    extern __shared__ float sm[];
    float* ws = sm;             // [64][192]
    float* xs = sm + 64*192;    // [64][65] (padded)
    const int tid = threadIdx.x;

    for (int i = tid; i < 64*64; i += 256) {
        int k = i >> 6, n = i & 63;
        ws[k*192 + n]       = wq[i];
        ws[k*192 + 64 + n]  = wk[i];
        ws[k*192 + 128 + n] = wv[i];
    }
    const int pix0 = blockIdx.x * 64;
    for (int i = tid; i < 64*64; i += 256) {
        int m = i >> 6, k = i & 63;
        xs[m*65 + k] = x[(pix0 + m)*64 + k];
    }
    __syncthreads();

    const int ty = tid >> 4, tx = tid & 15;
    float acc[4][12];
    #pragma unroll
    for (int i = 0; i < 4; i++)
        #pragma unroll
        for (int j = 0; j < 12; j++) acc[i][j] = 0.f;

    for (int k = 0; k < 64; k++) {
        float a[4], b[12];
        #pragma unroll
        for (int i = 0; i < 4; i++) a[i] = xs[(ty + 16*i)*65 + k];
        #pragma unroll
        for (int j = 0; j < 12; j++) b[j] = ws[k*192 + tx + 16*j];
        #pragma unroll
        for (int i = 0; i < 4; i++)
            #pragma unroll
            for (int j = 0; j < 12; j++) acc[i][j] = fmaf(a[i], b[j], acc[i][j]);
    }

    #pragma unroll
    for (int i = 0; i < 4; i++) {
        const int m = pix0 + ty + 16*i;
        #pragma unroll
        for (int j = 0; j < 12; j++) {
            const int n = tx + 16*j;
            float* dst = (n < 64) ? g_q : ((n < 128) ? g_k : g_v);
            dst[m*64 + (n & 63)] = acc[i][j];
        }
    }
}

// ---------------------------------------------------------------------------
// Kernel B: fused 3x3 windowed attention + LN1 + FFN + LN2 + fuse-conv + BN + relu
// Block: 64 consecutive pixels in one image row. 256 threads.
//   attention/LN phases: thread = (pixel p = tid>>2, head hd = tid&3)
//   GEMM phases: 16x16 thread grid, register tiles.
// smem misc layout (s_m):
//   [0:64)   ln1_g   [64:128) ln1_b   [128:192) ln2_g  [192:256) ln2_b
//   [256:384) ff1_b  [384:448) ff2_b  [448:512) bn scale  [512:576) bn shift
// ---------------------------------------------------------------------------
__global__ void __launch_bounds__(256) attn_ffn_kernel(
    const float* __restrict__ x,
    const float* __restrict__ ln1_g, const float* __restrict__ ln1_b,
    const float* __restrict__ ff1_w, const float* __restrict__ ff1_b,
    const float* __restrict__ ff2_w, const float* __restrict__ ff2_b,
    const float* __restrict__ ln2_g, const float* __restrict__ ln2_b,
    const float* __restrict__ w_fuse,
    const float* __restrict__ bn_g, const float* __restrict__ bn_b,
    const float* __restrict__ bn_mean, const float* __restrict__ bn_var,
    float* __restrict__ out)
{
    extern __shared__ float sm[];
    float* s_w = sm;             // 8192 floats: phase-shared weight buffer
    float* s_o = s_w + 8192;     // [64][65]
    float* s_h = s_o + 64*65;    // [64][129]
    float* s_m = s_h + 64*129;   // 576 floats misc

    const int tid = threadIdx.x;
    if (tid < 64) {
        s_m[tid]        = ln1_g[tid];
        s_m[64 + tid]   = ln1_b[tid];
        s_m[128 + tid]  = ln2_g[tid];
        s_m[192 + tid]  = ln2_b[tid];
        s_m[384 + tid]  = ff2_b[tid];
        float sc = bn_g[tid] * rsqrtf(bn_var[tid] + 1e-3f);
        s_m[448 + tid]  = sc;
        s_m[512 + tid]  = bn_b[tid] - bn_mean[tid]*sc;
    } else if (tid < 192) {
        s_m[256 + (tid - 64)] = ff1_b[tid - 64];
    }
    __syncthreads();

    const int b  = blockIdx.z;
    const int yy = blockIdx.y;
    const int c0 = blockIdx.x * 64;

    // ---------------- attention: thread = (pixel, head) ----------------
    const int p  = tid >> 2;
    const int hd = tid & 3;
    const int px = c0 + p;
    const int base = ((b*HDIM + yy)*WDIM + px) * 64;

    float q[16];
    {
        const float* qp = g_q + base + hd*16;
        #pragma unroll
        for (int d = 0; d < 16; d++) q[d] = qp[d];
    }

    float sc9[9];
    #pragma unroll
    for (int o = 0; o < 9; o++) {
        const int dy = o/3 - 1, dx = o%3 - 1;
        const int ny = yy + dy, nx = px + dx;
        float s = 0.f;
        if ((unsigned)ny < HDIM && (unsigned)nx < WDIM) {
            const float* kp = g_k + ((b*HDIM + ny)*WDIM + nx)*64 + hd*16;
            #pragma unroll
            for (int d = 0; d < 16; d++) s = fmaf(q[d], kp[d], s);
        }
        sc9[o] = s * 0.25f;   // / sqrt(16)
    }

    float mx = sc9[0];
    #pragma unroll
    for (int o = 1; o < 9; o++) mx = fmaxf(mx, sc9[o]);
    float ssum = 0.f;
    #pragma unroll
    for (int o = 0; o < 9; o++) { sc9[o] = __expf(sc9[o] - mx); ssum += sc9[o]; }
    const float sinv = 1.f / ssum;

    float acc[16];
    #pragma unroll
    for (int d = 0; d < 16; d++) acc[d] = 0.f;
    #pragma unroll
    for (int o = 0; o < 9; o++) {
        const int dy = o/3 - 1, dx = o%3 - 1;
        const int ny = yy + dy, nx = px + dx;
        if ((unsigned)ny < HDIM && (unsigned)nx < WDIM) {
            const float w = sc9[o] * sinv;
            const float* vp = g_v + ((b*HDIM + ny)*WDIM + nx)*64 + hd*16;
            #pragma unroll
            for (int d = 0; d < 16; d++) acc[d] = fmaf(w, vp[d], acc[d]);
        }
    }

    // ---------------- LN1 with residual (4 lanes/pixel, shfl reduce) ----------------
    {
        const float* xp = x + base + hd*16;
        float val[16], s1 = 0.f, s2 = 0.f;
        #pragma unroll
        for (int d = 0; d < 16; d++) {
            val[d] = acc[d] + xp[d];
            s1 += val[d];
            s2 = fmaf(val[d], val[d], s2);
        }
        s1 += __shfl_xor_sync(0xffffffff, s1, 1);
        s2 += __shfl_xor_sync(0xffffffff, s2, 1);
        s1 += __shfl_xor_sync(0xffffffff, s1, 2);
        s2 += __shfl_xor_sync(0xffffffff, s2, 2);
        const float mean = s1 * (1.f/64.f);
        const float var  = s2 * (1.f/64.f) - mean*mean;
        const float rstd = rsqrtf(var + 1e-3f);
        #pragma unroll
        for (int d = 0; d < 16; d++) {
            const int c = hd*16 + d;
            s_o[p*65 + c] = (val[d] - mean)*rstd*s_m[c] + s_m[64 + c];
        }
    }

    // load ff1 weights
    for (int i = tid; i < 64*128; i += 256) s_w[i] = ff1_w[i];
    __syncthreads();

    const int ty = tid >> 4, tx = tid & 15;

    // ---------------- GEMM1: h = relu(o @ ff1 + b1)  [64x128, K=64] ----------------
    {
        float a1[4][8];
        #pragma unroll
        for (int i = 0; i < 4; i++)
            #pragma unroll
            for (int j = 0; j < 8; j++) a1[i][j] = 0.f;
        for (int k = 0; k < 64; k++) {
            float a[4], bb[8];
            #pragma unroll
            for (int i = 0; i < 4; i++) a[i] = s_o[(ty + 16*i)*65 + k];
            #pragma unroll
            for (int j = 0; j < 8; j++) bb[j] = s_w[k*128 + tx + 16*j];
            #pragma unroll
            for (int i = 0; i < 4; i++)
                #pragma unroll
                for (int j = 0; j < 8; j++) a1[i][j] = fmaf(a[i], bb[j], a1[i][j]);
        }
        #pragma unroll
        for (int i = 0; i < 4; i++) {
            const int m = ty + 16*i;
            #pragma unroll
            for (int j = 0; j < 8; j++) {
                const int n = tx + 16*j;
                s_h[m*129 + n] = fmaxf(a1[i][j] + s_m[256 + n], 0.f);
            }
        }
    }
    __syncthreads();
    for (int i = tid; i < 128*64; i += 256) s_w[i] = ff2_w[i];
    __syncthreads();

    // ---------------- GEMM2: y = h @ ff2 + b2, accumulate into o  [64x64, K=128] ----------------
    {
        float a2[4][4];
        #pragma unroll
        for (int i = 0; i < 4; i++)
            #pragma unroll
            for (int j = 0; j < 4; j++) a2[i][j] = 0.f;
        for (int k = 0; k < 128; k++) {
            float a[4], bb[4];
            #pragma unroll
            for (int i = 0; i < 4; i++) a[i] = s_h[(ty + 16*i)*129 + k];
            #pragma unroll
            for (int j = 0; j < 4; j++) bb[j] = s_w[k*64 + tx + 16*j];
            #pragma unroll
            for (int i = 0; i < 4; i++)
                #pragma unroll
                for (int j = 0; j < 4; j++) a2[i][j] = fmaf(a[i], bb[j], a2[i][j]);
        }
        #pragma unroll
        for (int i = 0; i < 4; i++) {
            const int m = ty + 16*i;
            #pragma unroll
            for (int j = 0; j < 4; j++) {
                const int n = tx + 16*j;
                s_o[m*65 + n] += a2[i][j] + s_m[384 + n];
            }
        }
    }
    __syncthreads();

    // ---------------- LN2 (4 lanes/pixel, shfl reduce) ----------------
    {
        float v2[16], s1 = 0.f, s2 = 0.f;
        #pragma unroll
        for (int d = 0; d < 16; d++) {
            v2[d] = s_o[p*65 + hd*16 + d];
            s1 += v2[d];
            s2 = fmaf(v2[d], v2[d], s2);
        }
        s1 += __shfl_xor_sync(0xffffffff, s1, 1);
        s2 += __shfl_xor_sync(0xffffffff, s2, 1);
        s1 += __shfl_xor_sync(0xffffffff, s1, 2);
        s2 += __shfl_xor_sync(0xffffffff, s2, 2);
        const float mean = s1 * (1.f/64.f);
        const float var  = s2 * (1.f/64.f) - mean*mean;
        const float rstd = rsqrtf(var + 1e-3f);
        #pragma unroll
        for (int d = 0; d < 16; d++) {
            const int c = hd*16 + d;
            s_o[p*65 + c] = (v2[d] - mean)*rstd*s_m[128 + c] + s_m[192 + c];
        }
    }
    __syncthreads();
    for (int i = tid; i < 64*64; i += 256) s_w[i] = w_fuse[i];
    __syncthreads();

    // ---------------- fuse 1x1 conv + BN + relu  [64x64, K=64] ----------------
    {
        float a3[4][4];
        #pragma unroll
        for (int i = 0; i < 4; i++)
            #pragma unroll
            for (int j = 0; j < 4; j++) a3[i][j] = 0.f;
        for (int k = 0; k < 64; k++) {
            float a[4], bb[4];
            #pragma unroll
            for (int i = 0; i < 4; i++) a[i] = s_o[(ty + 16*i)*65 + k];
            #pragma unroll
            for (int j = 0; j < 4; j++) bb[j] = s_w[k*64 + tx + 16*j];
            #pragma unroll
            for (int i = 0; i < 4; i++)
                #pragma unroll
                for (int j = 0; j < 4; j++) a3[i][j] = fmaf(a[i], bb[j], a3[i][j]);
        }
        #pragma unroll
        for (int i = 0; i < 4; i++) {
            const int m = ty + 16*i;
            #pragma unroll
            for (int j = 0; j < 4; j++) {
                const int n = tx + 16*j;
                const float r = a3[i][j]*s_m[448 + n] + s_m[512 + n];
                out[((b*HDIM + yy)*WDIM + c0 + m)*64 + n] = fmaxf(r, 0.f);
            }
        }
    }
}

extern "C" void kernel_launch(void* const* d_in, const int* in_sizes, int n_in,
                              void* d_out, int out_size)
{
    const float* x      = (const float*)d_in[0];
    const float* wq     = (const float*)d_in[1];
    const float* wk     = (const float*)d_in[2];
    const float* wv     = (const float*)d_in[3];
    const float* ln1_g  = (const float*)d_in[4];
    const float* ln1_b  = (const float*)d_in[5];
    const float* ff1_w  = (const float*)d_in[6];
    const float* ff1_b  = (const float*)d_in[7];
    const float* ff2_w  = (const float*)d_in[8];
    const float* ff2_b  = (const float*)d_in[9];
    const float* ln2_g  = (const float*)d_in[10];
    const float* ln2_b  = (const float*)d_in[11];
    const float* w_fuse = (const float*)d_in[12];
    const float* bn_g   = (const float*)d_in[13];
    const float* bn_b   = (const float*)d_in[14];
    const float* bn_mean= (const float*)d_in[15];
    const float* bn_var = (const float*)d_in[16];
    float* out = (float*)d_out;

    const int SMEM_A = (64*192 + 64*65) * 4;                 // 65792 B
    const int SMEM_B = (8192 + 64*65 + 64*129 + 576) * 4;    // 84736 B
    cudaFuncSetAttribute(qkv_kernel, cudaFuncAttributeMaxDynamicSharedMemorySize, SMEM_A);
    cudaFuncSetAttribute(attn_ffn_kernel, cudaFuncAttributeMaxDynamicSharedMemorySize, SMEM_B);

    qkv_kernel<<<NPIX/64, 256, SMEM_A>>>(x, wq, wk, wv);

    dim3 grid(WDIM/64, HDIM, BATCH);
    attn_ffn_kernel<<<grid, 256, SMEM_B>>>(
        x, ln1_g, ln1_b, ff1_w, ff1_b, ff2_w, ff2_b,
        ln2_g, ln2_b, w_fuse, bn_g, bn_b, bn_mean, bn_var, out);
}

// round 2
// speedup vs baseline: 1.5371x; 1.5371x over previous
#include <cuda_runtime.h>

#define BATCH 4
#define HDIM 384
#define WDIM 384
#define NPIX (BATCH*HDIM*WDIM)

// Scratch for q,k,v projections (__device__ globals: allocation-guard-safe)
__device__ float g_q[NPIX*64];
__device__ float g_k[NPIX*64];
__device__ float g_v[NPIX*64];

// ---------------------------------------------------------------------------
// Kernel A: q,k,v = x @ [wq|wk|wv]   (64-pixel tile) x (64x192)
// 256 threads = 16x16; thread tile m={4ty..4ty+3}, n={4tx,64+4tx,128+4tx}
// ---------------------------------------------------------------------------
__global__ void __launch_bounds__(256,2) qkv_kernel(
    const float* __restrict__ x,
    const float* __restrict__ wq,
    const float* __restrict__ wk,
    const float* __restrict__ wv)
{
    extern __shared__ float sm[];
    float* ws = sm;            // [64][192]
    float* xs = sm + 12288;    // [64][68]
    const int tid = threadIdx.x;

    for (int i = tid; i < 4096; i += 256) {
        int k = i >> 6, n = i & 63;
        ws[k*192 + n]       = wq[i];
        ws[k*192 + 64 + n]  = wk[i];
        ws[k*192 + 128 + n] = wv[i];
    }
    const int pix0 = blockIdx.x * 64;
    const float4* xg = (const float4*)(x + pix0*64);
    for (int i = tid; i < 1024; i += 256) {
        int m = i >> 4, c4 = i & 15;
        *(float4*)&xs[m*68 + c4*4] = xg[i];
    }
    __syncthreads();

    const int ty = tid >> 4, tx = tid & 15;
    float acc[4][12];
    #pragma unroll
    for (int i = 0; i < 4; i++)
        #pragma unroll
        for (int j = 0; j < 12; j++) acc[i][j] = 0.f;

    for (int k = 0; k < 64; k += 4) {
        float av[4][4];
        #pragma unroll
        for (int i = 0; i < 4; i++)
            *(float4*)av[i] = *(const float4*)&xs[(4*ty + i)*68 + k];
        #pragma unroll
        for (int kk = 0; kk < 4; kk++) {
            float4 b0 = *(const float4*)&ws[(k+kk)*192 + 4*tx];
            float4 b1 = *(const float4*)&ws[(k+kk)*192 + 64 + 4*tx];
            float4 b2 = *(const float4*)&ws[(k+kk)*192 + 128 + 4*tx];
            #pragma unroll
            for (int i = 0; i < 4; i++) {
                float a = av[i][kk];
                acc[i][0]  = fmaf(a, b0.x, acc[i][0]);
                acc[i][1]  = fmaf(a, b0.y, acc[i][1]);
                acc[i][2]  = fmaf(a, b0.z, acc[i][2]);
                acc[i][3]  = fmaf(a, b0.w, acc[i][3]);
                acc[i][4]  = fmaf(a, b1.x, acc[i][4]);
                acc[i][5]  = fmaf(a, b1.y, acc[i][5]);
                acc[i][6]  = fmaf(a, b1.z, acc[i][6]);
                acc[i][7]  = fmaf(a, b1.w, acc[i][7]);
                acc[i][8]  = fmaf(a, b2.x, acc[i][8]);
                acc[i][9]  = fmaf(a, b2.y, acc[i][9]);
                acc[i][10] = fmaf(a, b2.z, acc[i][10]);
                acc[i][11] = fmaf(a, b2.w, acc[i][11]);
            }
        }
    }
    #pragma unroll
    for (int i = 0; i < 4; i++) {
        const int m = pix0 + 4*ty + i;
        *(float4*)&g_q[m*64 + 4*tx] = make_float4(acc[i][0], acc[i][1], acc[i][2],  acc[i][3]);
        *(float4*)&g_k[m*64 + 4*tx] = make_float4(acc[i][4], acc[i][5], acc[i][6],  acc[i][7]);
        *(float4*)&g_v[m*64 + 4*tx] = make_float4(acc[i][8], acc[i][9], acc[i][10], acc[i][11]);
    }
}

// ---------------------------------------------------------------------------
// Kernel B: fused 3x3 attention + LN1 + FFN + LN2 + fuse conv + BN + relu
// 64 pixels of one image row per block. 256 threads.
// smem (floats):
//   region1 [0,16640): halo (198*68=13464)  |  s_w(8192) + s_h(64*132=8448)
//   region2 [16640,20992): s_q | s_o (both 64*68=4352)
//   s_m     [20992,21568)
// ---------------------------------------------------------------------------
#define R1 0
#define R2 16640
#define MOFF 20992
#define SMB_FLOATS 21568

__global__ void __launch_bounds__(256,2) attn_ffn_kernel(
    const float* __restrict__ x,
    const float* __restrict__ ln1_g, const float* __restrict__ ln1_b,
    const float* __restrict__ ff1_w, const float* __restrict__ ff1_b,
    const float* __restrict__ ff2_w, const float* __restrict__ ff2_b,
    const float* __restrict__ ln2_g, const float* __restrict__ ln2_b,
    const float* __restrict__ w_fuse,
    const float* __restrict__ bn_g, const float* __restrict__ bn_b,
    const float* __restrict__ bn_mean, const float* __restrict__ bn_var,
    float* __restrict__ out)
{
    extern __shared__ float sm[];
    float* s_halo = sm + R1;          // [198][68]  (k, then v)
    float* s_w    = sm + R1;          // [*][n] weight buffer (aliases halo)
    float* s_h    = sm + R1 + 8192;   // [64][132]
    float* s_q    = sm + R2;          // [64][68]
    float* s_o    = sm + R2;          // [64][68]  (aliases s_q; live after attn)
    float* s_m    = sm + MOFF;

    const int tid = threadIdx.x;
    if (tid < 64) {
        s_m[tid]        = ln1_g[tid];
        s_m[64 + tid]   = ln1_b[tid];
        s_m[128 + tid]  = ln2_g[tid];
        s_m[192 + tid]  = ln2_b[tid];
        s_m[384 + tid]  = ff2_b[tid];
        float sc = bn_g[tid] * rsqrtf(bn_var[tid] + 1e-3f);
        s_m[448 + tid]  = sc;
        s_m[512 + tid]  = bn_b[tid] - bn_mean[tid]*sc;
    } else if (tid < 192) {
        s_m[256 + (tid - 64)] = ff1_b[tid - 64];
    }

    const int b  = blockIdx.z;
    const int yy = blockIdx.y;
    const int c0 = blockIdx.x * 64;

    // ---- stage q (coalesced: the block's 64 rows are contiguous) ----
    {
        const float4* qg = (const float4*)(g_q + ((b*HDIM + yy)*WDIM + c0)*64);
        for (int i = tid; i < 1024; i += 256) {
            int m = i >> 4, c4 = i & 15;
            *(float4*)&s_q[m*68 + c4*4] = qg[i];
        }
    }
    // ---- stage k halo: rows yy-1..yy+1, px c0-1..c0+64, zero-filled ----
    for (int idx = tid; idx < 3168; idx += 256) {
        int e = idx >> 4, c4 = idx & 15;
        int r = e / 66, j = e - r*66;
        int gy = yy + r - 1, gx = c0 + j - 1;
        float4 v = make_float4(0.f, 0.f, 0.f, 0.f);
        if ((unsigned)gy < HDIM && (unsigned)gx < WDIM)
            v = *(const float4*)(g_k + ((b*HDIM + gy)*WDIM + gx)*64 + c4*4);
        *(float4*)&s_halo[e*68 + c4*4] = v;
    }
    __syncthreads();

    // ---- scores ----
    const int p  = tid >> 2;
    const int hd = tid & 3;
    const int base = ((b*HDIM + yy)*WDIM + c0 + p)*64;

    float q[16];
    #pragma unroll
    for (int i = 0; i < 4; i++)
        *(float4*)&q[4*i] = *(const float4*)&s_q[p*68 + hd*16 + 4*i];

    float sc9[9];
    #pragma unroll
    for (int o = 0; o < 9; o++) {
        const int r = o / 3, dxo = o % 3;
        const float* kp = &s_halo[(r*66 + p + dxo)*68 + hd*16];
        float s = 0.f;
        #pragma unroll
        for (int i = 0; i < 4; i++) {
            float4 kk = *(const float4*)&kp[4*i];
            s = fmaf(q[4*i+0], kk.x, s);
            s = fmaf(q[4*i+1], kk.y, s);
            s = fmaf(q[4*i+2], kk.z, s);
            s = fmaf(q[4*i+3], kk.w, s);
        }
        sc9[o] = s * 0.25f;
    }
    float mx = sc9[0];
    #pragma unroll
    for (int o = 1; o < 9; o++) mx = fmaxf(mx, sc9[o]);
    float ssum = 0.f;
    #pragma unroll
    for (int o = 0; o < 9; o++) { sc9[o] = __expf(sc9[o] - mx); ssum += sc9[o]; }
    const float sinv = 1.f / ssum;

    // prefetch residual x into registers (hide latency behind v staging)
    float xr[16];
    #pragma unroll
    for (int i = 0; i < 4; i++)
        *(float4*)&xr[4*i] = *(const float4*)(x + base + hd*16 + 4*i);

    __syncthreads();
    // ---- stage v halo over k halo ----
    for (int idx = tid; idx < 3168; idx += 256) {
        int e = idx >> 4, c4 = idx & 15;
        int r = e / 66, j = e - r*66;
        int gy = yy + r - 1, gx = c0 + j - 1;
        float4 v = make_float4(0.f, 0.f, 0.f, 0.f);
        if ((unsigned)gy < HDIM && (unsigned)gx < WDIM)
            v = *(const float4*)(g_v + ((b*HDIM + gy)*WDIM + gx)*64 + c4*4);
        *(float4*)&s_halo[e*68 + c4*4] = v;
    }
    __syncthreads();

    // ---- weighted sum of v ----
    float acc[16];
    #pragma unroll
    for (int d = 0; d < 16; d++) acc[d] = 0.f;
    #pragma unroll
    for (int o = 0; o < 9; o++) {
        const int r = o / 3, dxo = o % 3;
        const float w = sc9[o] * sinv;
        const float* vp = &s_halo[(r*66 + p + dxo)*68 + hd*16];
        #pragma unroll
        for (int i = 0; i < 4; i++) {
            float4 vv = *(const float4*)&vp[4*i];
            acc[4*i+0] = fmaf(w, vv.x, acc[4*i+0]);
            acc[4*i+1] = fmaf(w, vv.y, acc[4*i+1]);
            acc[4*i+2] = fmaf(w, vv.z, acc[4*i+2]);
            acc[4*i+3] = fmaf(w, vv.w, acc[4*i+3]);
        }
    }

    // ---- LN1 with residual (shfl over 4 lanes of pixel) ----
    {
        float s1 = 0.f, s2 = 0.f;
        #pragma unroll
        for (int d = 0; d < 16; d++) {
            acc[d] += xr[d];
            s1 += acc[d];
            s2 = fmaf(acc[d], acc[d], s2);
        }
        s1 += __shfl_xor_sync(0xffffffff, s1, 1);
        s2 += __shfl_xor_sync(0xffffffff, s2, 1);
        s1 += __shfl_xor_sync(0xffffffff, s1, 2);
        s2 += __shfl_xor_sync(0xffffffff, s2, 2);
        const float mean = s1 * (1.f/64.f);
        const float var  = s2 * (1.f/64.f) - mean*mean;
        const float rstd = rsqrtf(var + 1e-3f);
        #pragma unroll
        for (int i = 0; i < 4; i++) {
            const int c = hd*16 + 4*i;
            float4 w4;
            w4.x = (acc[4*i+0] - mean)*rstd*s_m[c+0] + s_m[64+c+0];
            w4.y = (acc[4*i+1] - mean)*rstd*s_m[c+1] + s_m[64+c+1];
            w4.z = (acc[4*i+2] - mean)*rstd*s_m[c+2] + s_m[64+c+2];
            w4.w = (acc[4*i+3] - mean)*rstd*s_m[c+3] + s_m[64+c+3];
            *(float4*)&s_o[p*68 + c] = w4;   // s_q dead; aliased region
        }
    }
    __syncthreads();

    // ---- stage ff1 (overwrites halo region) ----
    {
        const float4* wg = (const float4*)ff1_w;
        for (int i = tid; i < 2048; i += 256) *(float4*)&s_w[4*i] = wg[i];
    }
    __syncthreads();

    const int ty = tid >> 4, tx = tid & 15;

    // ---- GEMM1: h = relu(o @ ff1 + b1)  [64x128, K=64] ----
    {
        float a1[4][8];
        #pragma unroll
        for (int i = 0; i < 4; i++)
            #pragma unroll
            for (int j = 0; j < 8; j++) a1[i][j] = 0.f;
        for (int k = 0; k < 64; k += 4) {
            float av[4][4];
            #pragma unroll
            for (int i = 0; i < 4; i++)
                *(float4*)av[i] = *(const float4*)&s_o[(4*ty+i)*68 + k];
            #pragma unroll
            for (int kk = 0; kk < 4; kk++) {
                float4 b0 = *(const float4*)&s_w[(k+kk)*128 + 4*tx];
                float4 b1 = *(const float4*)&s_w[(k+kk)*128 + 64 + 4*tx];
                #pragma unroll
                for (int i = 0; i < 4; i++) {
                    float a = av[i][kk];
                    a1[i][0] = fmaf(a, b0.x, a1[i][0]);
                    a1[i][1] = fmaf(a, b0.y, a1[i][1]);
                    a1[i][2] = fmaf(a, b0.z, a1[i][2]);
                    a1[i][3] = fmaf(a, b0.w, a1[i][3]);
                    a1[i][4] = fmaf(a, b1.x, a1[i][4]);
                    a1[i][5] = fmaf(a, b1.y, a1[i][5]);
                    a1[i][6] = fmaf(a, b1.z, a1[i][6]);
                    a1[i][7] = fmaf(a, b1.w, a1[i][7]);
                }
            }
        }
        #pragma unroll
        for (int i = 0; i < 4; i++) {
            const int m = 4*ty + i;
            float4 h0, h1;
            h0.x = fmaxf(a1[i][0] + s_m[256 + 4*tx+0], 0.f);
            h0.y = fmaxf(a1[i][1] + s_m[256 + 4*tx+1], 0.f);
            h0.z = fmaxf(a1[i][2] + s_m[256 + 4*tx+2], 0.f);
            h0.w = fmaxf(a1[i][3] + s_m[256 + 4*tx+3], 0.f);
            h1.x = fmaxf(a1[i][4] + s_m[256 + 64 + 4*tx+0], 0.f);
            h1.y = fmaxf(a1[i][5] + s_m[256 + 64 + 4*tx+1], 0.f);
            h1.z = fmaxf(a1[i][6] + s_m[256 + 64 + 4*tx+2], 0.f);
            h1.w = fmaxf(a1[i][7] + s_m[256 + 64 + 4*tx+3], 0.f);
            *(float4*)&s_h[m*132 + 4*tx]      = h0;
            *(float4*)&s_h[m*132 + 64 + 4*tx] = h1;
        }
    }
    __syncthreads();
    {
        const float4* wg = (const float4*)ff2_w;
        for (int i = tid; i < 2048; i += 256) *(float4*)&s_w[4*i] = wg[i];
    }
    __syncthreads();

    // ---- GEMM2: o += h @ ff2 + b2  [64x64, K=128] ----
    {
        float a2[4][4];
        #pragma unroll
        for (int i = 0; i < 4; i++)
            #pragma unroll
            for (int j = 0; j < 4; j++) a2[i][j] = 0.f;
        for (int k = 0; k < 128; k += 4) {
            float av[4][4];
            #pragma unroll
            for (int i = 0; i < 4; i++)
                *(float4*)av[i] = *(const float4*)&s_h[(4*ty+i)*132 + k];
            #pragma unroll
            for (int kk = 0; kk < 4; kk++) {
                float4 b0 = *(const float4*)&s_w[(k+kk)*64 + 4*tx];
                #pragma unroll
                for (int i = 0; i < 4; i++) {
                    float a = av[i][kk];
                    a2[i][0] = fmaf(a, b0.x, a2[i][0]);
                    a2[i][1] = fmaf(a, b0.y, a2[i][1]);
                    a2[i][2] = fmaf(a, b0.z, a2[i][2]);
                    a2[i][3] = fmaf(a, b0.w, a2[i][3]);
                }
            }
        }
        #pragma unroll
        for (int i = 0; i < 4; i++) {
            const int m = 4*ty + i;
            float4 o4 = *(float4*)&s_o[m*68 + 4*tx];
            o4.x += a2[i][0] + s_m[384 + 4*tx+0];
            o4.y += a2[i][1] + s_m[384 + 4*tx+1];
            o4.z += a2[i][2] + s_m[384 + 4*tx+2];
            o4.w += a2[i][3] + s_m[384 + 4*tx+3];
            *(float4*)&s_o[m*68 + 4*tx] = o4;
        }
    }
    __syncthreads();

    // ---- LN2 ----
    {
        float v2[16], s1 = 0.f, s2 = 0.f;
        #pragma unroll
        for (int i = 0; i < 4; i++) {
            float4 t = *(const float4*)&s_o[p*68 + hd*16 + 4*i];
            v2[4*i+0] = t.x; v2[4*i+1] = t.y; v2[4*i+2] = t.z; v2[4*i+3] = t.w;
        }
        #pragma unroll
        for (int d = 0; d < 16; d++) { s1 += v2[d]; s2 = fmaf(v2[d], v2[d], s2); }
        s1 += __shfl_xor_sync(0xffffffff, s1, 1);
        s2 += __shfl_xor_sync(0xffffffff, s2, 1);
        s1 += __shfl_xor_sync(0xffffffff, s1, 2);
        s2 += __shfl_xor_sync(0xffffffff, s2, 2);
        const float mean = s1 * (1.f/64.f);
        const float var  = s2 * (1.f/64.f) - mean*mean;
        const float rstd = rsqrtf(var + 1e-3f);
        #pragma unroll
        for (int i = 0; i < 4; i++) {
            const int c = hd*16 + 4*i;
            float4 w4;
            w4.x = (v2[4*i+0] - mean)*rstd*s_m[128+c+0] + s_m[192+c+0];
            w4.y = (v2[4*i+1] - mean)*rstd*s_m[128+c+1] + s_m[192+c+1];
            w4.z = (v2[4*i+2] - mean)*rstd*s_m[128+c+2] + s_m[192+c+2];
            w4.w = (v2[4*i+3] - mean)*rstd*s_m[128+c+3] + s_m[192+c+3];
            *(float4*)&s_o[p*68 + c] = w4;
        }
    }
    __syncthreads();
    {
        const float4* wg = (const float4*)w_fuse;
        for (int i = tid; i < 1024; i += 256) *(float4*)&s_w[4*i] = wg[i];
    }
    __syncthreads();

    // ---- fuse 1x1 conv + BN + relu  [64x64, K=64] ----
    {
        float a3[4][4];
        #pragma unroll
        for (int i = 0; i < 4; i++)
            #pragma unroll
            for (int j = 0; j < 4; j++) a3[i][j] = 0.f;
        for (int k = 0; k < 64; k += 4) {
            float av[4][4];
            #pragma unroll
            for (int i = 0; i < 4; i++)
                *(float4*)av[i] = *(const float4*)&s_o[(4*ty+i)*68 + k];
            #pragma unroll
            for (int kk = 0; kk < 4; kk++) {
                float4 b0 = *(const float4*)&s_w[(k+kk)*64 + 4*tx];
                #pragma unroll
                for (int i = 0; i < 4; i++) {
                    float a = av[i][kk];
                    a3[i][0] = fmaf(a, b0.x, a3[i][0]);
                    a3[i][1] = fmaf(a, b0.y, a3[i][1]);
                    a3[i][2] = fmaf(a, b0.z, a3[i][2]);
                    a3[i][3] = fmaf(a, b0.w, a3[i][3]);
                }
            }
        }
        #pragma unroll
        for (int i = 0; i < 4; i++) {
            const int m = 4*ty + i;
            float4 r4;
            r4.x = fmaxf(a3[i][0]*s_m[448 + 4*tx+0] + s_m[512 + 4*tx+0], 0.f);
            r4.y = fmaxf(a3[i][1]*s_m[448 + 4*tx+1] + s_m[512 + 4*tx+1], 0.f);
            r4.z = fmaxf(a3[i][2]*s_m[448 + 4*tx+2] + s_m[512 + 4*tx+2], 0.f);
            r4.w = fmaxf(a3[i][3]*s_m[448 + 4*tx+3] + s_m[512 + 4*tx+3], 0.f);
            *(float4*)&out[((b*HDIM + yy)*WDIM + c0 + m)*64 + 4*tx] = r4;
        }
    }
}

extern "C" void kernel_launch(void* const* d_in, const int* in_sizes, int n_in,
                              void* d_out, int out_size)
{
    const float* x      = (const float*)d_in[0];
    const float* wq     = (const float*)d_in[1];
    const float* wk     = (const float*)d_in[2];
    const float* wv     = (const float*)d_in[3];
    const float* ln1_g  = (const float*)d_in[4];
    const float* ln1_b  = (const float*)d_in[5];
    const float* ff1_w  = (const float*)d_in[6];
    const float* ff1_b  = (const float*)d_in[7];
    const float* ff2_w  = (const float*)d_in[8];
    const float* ff2_b  = (const float*)d_in[9];
    const float* ln2_g  = (const float*)d_in[10];
    const float* ln2_b  = (const float*)d_in[11];
    const float* w_fuse = (const float*)d_in[12];
    const float* bn_g   = (const float*)d_in[13];
    const float* bn_b   = (const float*)d_in[14];
    const float* bn_mean= (const float*)d_in[15];
    const float* bn_var = (const float*)d_in[16];
    float* out = (float*)d_out;

    const int SMEM_A = (12288 + 64*68) * 4;     // 66560 B
    const int SMEM_B = SMB_FLOATS * 4;          // 86272 B
    cudaFuncSetAttribute(qkv_kernel, cudaFuncAttributeMaxDynamicSharedMemorySize, SMEM_A);
    cudaFuncSetAttribute(attn_ffn_kernel, cudaFuncAttributeMaxDynamicSharedMemorySize, SMEM_B);

    qkv_kernel<<<NPIX/64, 256, SMEM_A>>>(x, wq, wk, wv);

    dim3 grid(WDIM/64, HDIM, BATCH);
    attn_ffn_kernel<<<grid, 256, SMEM_B>>>(
        x, ln1_g, ln1_b, ff1_w, ff1_b, ff2_w, ff2_b,
        ln2_g, ln2_b, w_fuse, bn_g, bn_b, bn_mean, bn_var, out);
}

// round 3
// speedup vs baseline: 2.4852x; 1.6169x over previous
#include <cuda_runtime.h>

#define BATCH 4
#define HDIM 384
#define WDIM 384
#define NPIX (BATCH*HDIM*WDIM)

// Scratch for q,k,v projections (__device__ globals: allocation-guard-safe)
__device__ float g_q[NPIX*64];
__device__ float g_k[NPIX*64];
__device__ float g_v[NPIX*64];

__device__ __forceinline__ float tf32r(float x) {
    unsigned u;
    asm("cvt.rna.tf32.f32 %0, %1;" : "=r"(u) : "f"(x));
    return __uint_as_float(u);
}

__device__ __forceinline__ void mma_tf32(float* d,
    unsigned a0, unsigned a1, unsigned a2, unsigned a3,
    unsigned b0, unsigned b1)
{
    asm volatile("mma.sync.aligned.m16n8k8.row.col.f32.tf32.tf32.f32 "
        "{%0,%1,%2,%3}, {%4,%5,%6,%7}, {%8,%9}, {%0,%1,%2,%3};"
        : "+f"(d[0]), "+f"(d[1]), "+f"(d[2]), "+f"(d[3])
        : "r"(a0), "r"(a1), "r"(a2), "r"(a3), "r"(b0), "r"(b1));
}

// ---------------------------------------------------------------------------
// Kernel A: q,k,v = x @ [wq|wk|wv]  via tf32 mma. 64 pixels/block, 8 warps.
// ws [64][200] (B operand, stride%32==8), xs [64][68] (A operand, stride%32==4)
// ---------------------------------------------------------------------------
__global__ void __launch_bounds__(256,2) qkv_kernel(
    const float* __restrict__ x,
    const float* __restrict__ wq,
    const float* __restrict__ wk,
    const float* __restrict__ wv)
{
    extern __shared__ float sm[];
    float* ws = sm;            // [64][200]
    float* xs = sm + 12800;    // [64][68]
    const int tid = threadIdx.x;

    for (int i = tid; i < 4096; i += 256) {
        int k = i >> 6, n = i & 63;
        ws[k*200 + n]       = tf32r(wq[i]);
        ws[k*200 + 64 + n]  = tf32r(wk[i]);
        ws[k*200 + 128 + n] = tf32r(wv[i]);
    }
    const int pix0 = blockIdx.x * 64;
    const float4* xg = (const float4*)(x + pix0*64);
    for (int i = tid; i < 1024; i += 256) {
        int m = i >> 4, c4 = i & 15;
        float4 v = xg[i];
        v.x = tf32r(v.x); v.y = tf32r(v.y); v.z = tf32r(v.z); v.w = tf32r(v.w);
        *(float4*)&xs[m*68 + c4*4] = v;
    }
    __syncthreads();

    const int wid = tid >> 5, lane = tid & 31;
    const int gr = lane >> 2, tg = lane & 3;
    const int m0 = (wid >> 1) * 16;
    const int nb = (wid & 1) * 96;
    const unsigned* xs32 = (const unsigned*)xs;
    const unsigned* ws32 = (const unsigned*)ws;

    float d[12][4];
    #pragma unroll
    for (int j = 0; j < 12; j++)
        #pragma unroll
        for (int c = 0; c < 4; c++) d[j][c] = 0.f;

    #pragma unroll
    for (int k0 = 0; k0 < 64; k0 += 8) {
        unsigned a0 = xs32[(m0+gr)*68   + k0+tg];
        unsigned a1 = xs32[(m0+gr+8)*68 + k0+tg];
        unsigned a2 = xs32[(m0+gr)*68   + k0+tg+4];
        unsigned a3 = xs32[(m0+gr+8)*68 + k0+tg+4];
        #pragma unroll
        for (int j = 0; j < 12; j++) {
            int n0 = nb + j*8;
            unsigned b0 = ws32[(k0+tg)*200   + n0+gr];
            unsigned b1 = ws32[(k0+tg+4)*200 + n0+gr];
            mma_tf32(d[j], a0, a1, a2, a3, b0, b1);
        }
    }

    #pragma unroll
    for (int j = 0; j < 12; j++) {
        int n = nb + j*8 + 2*tg;
        float* dst; int nn;
        if (n < 64)       { dst = g_q; nn = n; }
        else if (n < 128) { dst = g_k; nn = n - 64; }
        else              { dst = g_v; nn = n - 128; }
        int m = pix0 + m0 + gr;
        *(float2*)&dst[m*64 + nn]     = make_float2(d[j][0], d[j][1]);
        *(float2*)&dst[(m+8)*64 + nn] = make_float2(d[j][2], d[j][3]);
    }
}

// ---------------------------------------------------------------------------
// Kernel B: fused 3x3 attention + LN1 + FFN + LN2 + fuse conv + BN + relu
// 64 pixels of one image row per block, 256 threads (8 warps).
// smem (floats):
//   region1 [0,13464): halo [198][68]  |  s_w [64][72]=4608 + s_h [64][132]=8448
//   region2 [13464,17816): s_q | s_o  [64][68]
//   s_m     [17816,18392)
// ---------------------------------------------------------------------------
#define R2OFF 13464
#define MOFF  17816
#define SMB_FLOATS 18392

__global__ void __launch_bounds__(256,3) attn_ffn_kernel(
    const float* __restrict__ x,
    const float* __restrict__ ln1_g, const float* __restrict__ ln1_b,
    const float* __restrict__ ff1_w, const float* __restrict__ ff1_b,
    const float* __restrict__ ff2_w, const float* __restrict__ ff2_b,
    const float* __restrict__ ln2_g, const float* __restrict__ ln2_b,
    const float* __restrict__ w_fuse,
    const float* __restrict__ bn_g, const float* __restrict__ bn_b,
    const float* __restrict__ bn_mean, const float* __restrict__ bn_var,
    float* __restrict__ out)
{
    extern __shared__ float sm[];
    float* s_halo = sm;               // [198][68]
    float* s_w    = sm;               // [64][72]   (aliases halo)
    float* s_h    = sm + 4608;        // [64][132]
    float* s_q    = sm + R2OFF;       // [64][68]
    float* s_o    = sm + R2OFF;       // alias of s_q
    float* s_m    = sm + MOFF;

    const int tid = threadIdx.x;
    if (tid < 64) {
        s_m[tid]        = ln1_g[tid];
        s_m[64 + tid]   = ln1_b[tid];
        s_m[128 + tid]  = ln2_g[tid];
        s_m[192 + tid]  = ln2_b[tid];
        s_m[384 + tid]  = ff2_b[tid];
        float sc = bn_g[tid] * rsqrtf(bn_var[tid] + 1e-3f);
        s_m[448 + tid]  = sc;
        s_m[512 + tid]  = bn_b[tid] - bn_mean[tid]*sc;
    } else if (tid < 192) {
        s_m[256 + (tid - 64)] = ff1_b[tid - 64];
    }

    const int b  = blockIdx.z;
    const int yy = blockIdx.y;
    const int c0 = blockIdx.x * 64;

    // ---- stage q ----
    {
        const float4* qg = (const float4*)(g_q + ((b*HDIM + yy)*WDIM + c0)*64);
        for (int i = tid; i < 1024; i += 256) {
            int m = i >> 4, c4 = i & 15;
            *(float4*)&s_q[m*68 + c4*4] = qg[i];
        }
    }
    // ---- stage k halo ----
    for (int idx = tid; idx < 3168; idx += 256) {
        int e = idx >> 4, c4 = idx & 15;
        int r = e / 66, j = e - r*66;
        int gy = yy + r - 1, gx = c0 + j - 1;
        float4 v = make_float4(0.f, 0.f, 0.f, 0.f);
        if ((unsigned)gy < HDIM && (unsigned)gx < WDIM)
            v = *(const float4*)(g_k + ((b*HDIM + gy)*WDIM + gx)*64 + c4*4);
        *(float4*)&s_halo[e*68 + c4*4] = v;
    }
    __syncthreads();

    // ---- attention scores (fp32) ----
    const int p  = tid >> 2;
    const int hd = tid & 3;
    const int base = ((b*HDIM + yy)*WDIM + c0 + p)*64;

    float q[16];
    #pragma unroll
    for (int i = 0; i < 4; i++)
        *(float4*)&q[4*i] = *(const float4*)&s_q[p*68 + hd*16 + 4*i];

    float sc9[9];
    #pragma unroll
    for (int o = 0; o < 9; o++) {
        const int r = o / 3, dxo = o % 3;
        const float* kp = &s_halo[(r*66 + p + dxo)*68 + hd*16];
        float s = 0.f;
        #pragma unroll
        for (int i = 0; i < 4; i++) {
            float4 kk = *(const float4*)&kp[4*i];
            s = fmaf(q[4*i+0], kk.x, s);
            s = fmaf(q[4*i+1], kk.y, s);
            s = fmaf(q[4*i+2], kk.z, s);
            s = fmaf(q[4*i+3], kk.w, s);
        }
        sc9[o] = s * 0.25f;
    }
    float mx = sc9[0];
    #pragma unroll
    for (int o = 1; o < 9; o++) mx = fmaxf(mx, sc9[o]);
    float ssum = 0.f;
    #pragma unroll
    for (int o = 0; o < 9; o++) { sc9[o] = __expf(sc9[o] - mx); ssum += sc9[o]; }
    const float sinv = 1.f / ssum;

    float xr[16];
    #pragma unroll
    for (int i = 0; i < 4; i++)
        *(float4*)&xr[4*i] = *(const float4*)(x + base + hd*16 + 4*i);

    __syncthreads();
    // ---- stage v halo ----
    for (int idx = tid; idx < 3168; idx += 256) {
        int e = idx >> 4, c4 = idx & 15;
        int r = e / 66, j = e - r*66;
        int gy = yy + r - 1, gx = c0 + j - 1;
        float4 v = make_float4(0.f, 0.f, 0.f, 0.f);
        if ((unsigned)gy < HDIM && (unsigned)gx < WDIM)
            v = *(const float4*)(g_v + ((b*HDIM + gy)*WDIM + gx)*64 + c4*4);
        *(float4*)&s_halo[e*68 + c4*4] = v;
    }
    __syncthreads();

    // ---- weighted sum of v ----
    float acc[16];
    #pragma unroll
    for (int d = 0; d < 16; d++) acc[d] = 0.f;
    #pragma unroll
    for (int o = 0; o < 9; o++) {
        const int r = o / 3, dxo = o % 3;
        const float w = sc9[o] * sinv;
        const float* vp = &s_halo[(r*66 + p + dxo)*68 + hd*16];
        #pragma unroll
        for (int i = 0; i < 4; i++) {
            float4 vv = *(const float4*)&vp[4*i];
            acc[4*i+0] = fmaf(w, vv.x, acc[4*i+0]);
            acc[4*i+1] = fmaf(w, vv.y, acc[4*i+1]);
            acc[4*i+2] = fmaf(w, vv.z, acc[4*i+2]);
            acc[4*i+3] = fmaf(w, vv.w, acc[4*i+3]);
        }
    }

    // ---- LN1 with residual; store tf32-rounded (A operand of GEMM1) ----
    {
        float s1 = 0.f, s2 = 0.f;
        #pragma unroll
        for (int d = 0; d < 16; d++) {
            acc[d] += xr[d];
            s1 += acc[d];
            s2 = fmaf(acc[d], acc[d], s2);
        }
        s1 += __shfl_xor_sync(0xffffffff, s1, 1);
        s2 += __shfl_xor_sync(0xffffffff, s2, 1);
        s1 += __shfl_xor_sync(0xffffffff, s1, 2);
        s2 += __shfl_xor_sync(0xffffffff, s2, 2);
        const float mean = s1 * (1.f/64.f);
        const float var  = s2 * (1.f/64.f) - mean*mean;
        const float rstd = rsqrtf(var + 1e-3f);
        #pragma unroll
        for (int i = 0; i < 4; i++) {
            const int c = hd*16 + 4*i;
            float4 w4;
            w4.x = tf32r((acc[4*i+0] - mean)*rstd*s_m[c+0] + s_m[64+c+0]);
            w4.y = tf32r((acc[4*i+1] - mean)*rstd*s_m[c+1] + s_m[64+c+1]);
            w4.z = tf32r((acc[4*i+2] - mean)*rstd*s_m[c+2] + s_m[64+c+2]);
            w4.w = tf32r((acc[4*i+3] - mean)*rstd*s_m[c+3] + s_m[64+c+3]);
            *(float4*)&s_o[p*68 + c] = w4;
        }
    }
    __syncthreads();   // halo reads done; LN1 visible

    const int wid = tid >> 5, lane = tid & 31;
    const int gr = lane >> 2, tg = lane & 3;
    const int m0 = (wid >> 1) * 16;
    const int wn = wid & 1;
    const unsigned* so32 = (const unsigned*)s_o;
    const unsigned* sh32 = (const unsigned*)s_h;
    const unsigned* sw32 = (const unsigned*)s_w;

    // ---- GEMM1: h = relu(o @ ff1 + b1), two n-halves ----
    #pragma unroll
    for (int P = 0; P < 2; P++) {
        for (int i = tid; i < 4096; i += 256) {
            int k = i >> 6, n = i & 63;
            s_w[k*72 + n] = tf32r(ff1_w[k*128 + P*64 + n]);
        }
        __syncthreads();
        float d1[4][4];
        #pragma unroll
        for (int j = 0; j < 4; j++)
            #pragma unroll
            for (int c = 0; c < 4; c++) d1[j][c] = 0.f;
        #pragma unroll
        for (int k0 = 0; k0 < 64; k0 += 8) {
            unsigned a0 = so32[(m0+gr)*68   + k0+tg];
            unsigned a1 = so32[(m0+gr+8)*68 + k0+tg];
            unsigned a2 = so32[(m0+gr)*68   + k0+tg+4];
            unsigned a3 = so32[(m0+gr+8)*68 + k0+tg+4];
            #pragma unroll
            for (int j = 0; j < 4; j++) {
                int n0 = wn*32 + j*8;
                unsigned b0 = sw32[(k0+tg)*72   + n0+gr];
                unsigned b1 = sw32[(k0+tg+4)*72 + n0+gr];
                mma_tf32(d1[j], a0, a1, a2, a3, b0, b1);
            }
        }
        #pragma unroll
        for (int j = 0; j < 4; j++) {
            int n = P*64 + wn*32 + j*8 + 2*tg;
            float bb0 = s_m[256 + n], bb1 = s_m[256 + n + 1];
            *(float2*)&s_h[(m0+gr)*132 + n] = make_float2(
                tf32r(fmaxf(d1[j][0] + bb0, 0.f)), tf32r(fmaxf(d1[j][1] + bb1, 0.f)));
            *(float2*)&s_h[(m0+gr+8)*132 + n] = make_float2(
                tf32r(fmaxf(d1[j][2] + bb0, 0.f)), tf32r(fmaxf(d1[j][3] + bb1, 0.f)));
        }
        __syncthreads();
    }

    // ---- GEMM2: o += h @ ff2 + b2, two k-halves ----
    float d2[4][4];
    #pragma unroll
    for (int j = 0; j < 4; j++)
        #pragma unroll
        for (int c = 0; c < 4; c++) d2[j][c] = 0.f;
    #pragma unroll
    for (int Kp = 0; Kp < 2; Kp++) {
        for (int i = tid; i < 4096; i += 256) {
            int k = i >> 6, n = i & 63;
            s_w[k*72 + n] = tf32r(ff2_w[(Kp*64 + k)*64 + n]);
        }
        __syncthreads();
        #pragma unroll
        for (int k0 = 0; k0 < 64; k0 += 8) {
            int kc = Kp*64 + k0;
            unsigned a0 = sh32[(m0+gr)*132   + kc+tg];
            unsigned a1 = sh32[(m0+gr+8)*132 + kc+tg];
            unsigned a2 = sh32[(m0+gr)*132   + kc+tg+4];
            unsigned a3 = sh32[(m0+gr+8)*132 + kc+tg+4];
            #pragma unroll
            for (int j = 0; j < 4; j++) {
                int n0 = wn*32 + j*8;
                unsigned b0 = sw32[(k0+tg)*72   + n0+gr];
                unsigned b1 = sw32[(k0+tg+4)*72 + n0+gr];
                mma_tf32(d2[j], a0, a1, a2, a3, b0, b1);
            }
        }
        __syncthreads();
    }
    #pragma unroll
    for (int j = 0; j < 4; j++) {
        int n = wn*32 + j*8 + 2*tg;
        float bb0 = s_m[384 + n], bb1 = s_m[384 + n + 1];
        float2 o0 = *(float2*)&s_o[(m0+gr)*68 + n];
        float2 o1 = *(float2*)&s_o[(m0+gr+8)*68 + n];
        *(float2*)&s_o[(m0+gr)*68 + n]   = make_float2(o0.x + d2[j][0] + bb0, o0.y + d2[j][1] + bb1);
        *(float2*)&s_o[(m0+gr+8)*68 + n] = make_float2(o1.x + d2[j][2] + bb0, o1.y + d2[j][3] + bb1);
    }
    __syncthreads();

    // ---- LN2; store tf32-rounded (A of GEMM3) ----
    {
        float v2[16], s1 = 0.f, s2 = 0.f;
        #pragma unroll
        for (int i = 0; i < 4; i++) {
            float4 t = *(const float4*)&s_o[p*68 + hd*16 + 4*i];
            v2[4*i+0] = t.x; v2[4*i+1] = t.y; v2[4*i+2] = t.z; v2[4*i+3] = t.w;
        }
        #pragma unroll
        for (int d = 0; d < 16; d++) { s1 += v2[d]; s2 = fmaf(v2[d], v2[d], s2); }
        s1 += __shfl_xor_sync(0xffffffff, s1, 1);
        s2 += __shfl_xor_sync(0xffffffff, s2, 1);
        s1 += __shfl_xor_sync(0xffffffff, s1, 2);
        s2 += __shfl_xor_sync(0xffffffff, s2, 2);
        const float mean = s1 * (1.f/64.f);
        const float var  = s2 * (1.f/64.f) - mean*mean;
        const float rstd = rsqrtf(var + 1e-3f);
        #pragma unroll
        for (int i = 0; i < 4; i++) {
            const int c = hd*16 + 4*i;
            float4 w4;
            w4.x = tf32r((v2[4*i+0] - mean)*rstd*s_m[128+c+0] + s_m[192+c+0]);
            w4.y = tf32r((v2[4*i+1] - mean)*rstd*s_m[128+c+1] + s_m[192+c+1]);
            w4.z = tf32r((v2[4*i+2] - mean)*rstd*s_m[128+c+2] + s_m[192+c+2]);
            w4.w = tf32r((v2[4*i+3] - mean)*rstd*s_m[128+c+3] + s_m[192+c+3]);
            *(float4*)&s_o[p*68 + c] = w4;
        }
    }
    // stage fuse weights (s_w; GEMM2 consumers done at last sync)
    for (int i = tid; i < 4096; i += 256) {
        int k = i >> 6, n = i & 63;
        s_w[k*72 + n] = tf32r(w_fuse[i]);
    }
    __syncthreads();

    // ---- GEMM3: fuse conv + BN + relu, direct global store ----
    {
        float d3[4][4];
        #pragma unroll
        for (int j = 0; j < 4; j++)
            #pragma unroll
            for (int c = 0; c < 4; c++) d3[j][c] = 0.f;
        #pragma unroll
        for (int k0 = 0; k0 < 64; k0 += 8) {
            unsigned a0 = so32[(m0+gr)*68   + k0+tg];
            unsigned a1 = so32[(m0+gr+8)*68 + k0+tg];
            unsigned a2 = so32[(m0+gr)*68   + k0+tg+4];
            unsigned a3 = so32[(m0+gr+8)*68 + k0+tg+4];
            #pragma unroll
            for (int j = 0; j < 4; j++) {
                int n0 = wn*32 + j*8;
                unsigned b0 = sw32[(k0+tg)*72   + n0+gr];
                unsigned b1 = sw32[(k0+tg+4)*72 + n0+gr];
                mma_tf32(d3[j], a0, a1, a2, a3, b0, b1);
            }
        }
        float* ob = out + ((b*HDIM + yy)*WDIM + c0)*64;
        #pragma unroll
        for (int j = 0; j < 4; j++) {
            int n = wn*32 + j*8 + 2*tg;
            float sc0 = s_m[448 + n], sc1 = s_m[448 + n + 1];
            float sh0 = s_m[512 + n], sh1 = s_m[512 + n + 1];
            *(float2*)&ob[(m0+gr)*64 + n] = make_float2(
                fmaxf(d3[j][0]*sc0 + sh0, 0.f), fmaxf(d3[j][1]*sc1 + sh1, 0.f));
            *(float2*)&ob[(m0+gr+8)*64 + n] = make_float2(
                fmaxf(d3[j][2]*sc0 + sh0, 0.f), fmaxf(d3[j][3]*sc1 + sh1, 0.f));
        }
    }
}

extern "C" void kernel_launch(void* const* d_in, const int* in_sizes, int n_in,
                              void* d_out, int out_size)
{
    const float* x      = (const float*)d_in[0];
    const float* wq     = (const float*)d_in[1];
    const float* wk     = (const float*)d_in[2];
    const float* wv     = (const float*)d_in[3];
    const float* ln1_g  = (const float*)d_in[4];
    const float* ln1_b  = (const float*)d_in[5];
    const float* ff1_w  = (const float*)d_in[6];
    const float* ff1_b  = (const float*)d_in[7];
    const float* ff2_w  = (const float*)d_in[8];
    const float* ff2_b  = (const float*)d_in[9];
    const float* ln2_g  = (const float*)d_in[10];
    const float* ln2_b  = (const float*)d_in[11];
    const float* w_fuse = (const float*)d_in[12];
    const float* bn_g   = (const float*)d_in[13];
    const float* bn_b   = (const float*)d_in[14];
    const float* bn_mean= (const float*)d_in[15];
    const float* bn_var = (const float*)d_in[16];
    float* out = (float*)d_out;

    const int SMEM_A = (12800 + 64*68) * 4;   // 68608 B
    const int SMEM_B = SMB_FLOATS * 4;        // 73568 B
    cudaFuncSetAttribute(qkv_kernel, cudaFuncAttributeMaxDynamicSharedMemorySize, SMEM_A);
    cudaFuncSetAttribute(attn_ffn_kernel, cudaFuncAttributeMaxDynamicSharedMemorySize, SMEM_B);

    qkv_kernel<<<NPIX/64, 256, SMEM_A>>>(x, wq, wk, wv);

    dim3 grid(WDIM/64, HDIM, BATCH);
    attn_ffn_kernel<<<grid, 256, SMEM_B>>>(
        x, ln1_g, ln1_b, ff1_w, ff1_b, ff2_w, ff2_b,
        ln2_g, ln2_b, w_fuse, bn_g, bn_b, bn_mean, bn_var, out);
}

// round 4
// speedup vs baseline: 2.7456x; 1.1048x over previous
#include <cuda_runtime.h>

#define BATCH 4
#define HDIM 384
#define WDIM 384
#define NPIX (BATCH*HDIM*WDIM)

// Scratch (static __device__: allocation-guard-safe)
__device__ float g_q[NPIX*64];
__device__ float g_k[NPIX*64];
__device__ float g_v[NPIX*64];
// Pre-converted tf32 weights in smem-ready padded layouts
__device__ float g_wqkv[64*200];      // [k][200]: wq|wk|wv cols 0..191
__device__ float g_ff1h[2*64*72];     // half P: [k][72] = ff1_w[k][P*64+n]
__device__ float g_ff2h[2*64*72];     // half Kp: [k][72] = ff2_w[Kp*64+k][n]
__device__ float g_wfuse72[64*72];    // [k][72]

__device__ __forceinline__ float tf32r(float x) {
    unsigned u;
    asm("cvt.rna.tf32.f32 %0, %1;" : "=r"(u) : "f"(x));
    return __uint_as_float(u);
}

__device__ __forceinline__ void mma_tf32(float* d,
    unsigned a0, unsigned a1, unsigned a2, unsigned a3,
    unsigned b0, unsigned b1)
{
    asm volatile("mma.sync.aligned.m16n8k8.row.col.f32.tf32.tf32.f32 "
        "{%0,%1,%2,%3}, {%4,%5,%6,%7}, {%8,%9}, {%0,%1,%2,%3};"
        : "+f"(d[0]), "+f"(d[1]), "+f"(d[2]), "+f"(d[3])
        : "r"(a0), "r"(a1), "r"(a2), "r"(a3), "r"(b0), "r"(b1));
}

// ---------------------------------------------------------------------------
// Weight prep: one-time tf32 conversion into padded layouts (35840 elements)
// ---------------------------------------------------------------------------
__global__ void __launch_bounds__(256) cvt_weights_kernel(
    const float* __restrict__ wq, const float* __restrict__ wk,
    const float* __restrict__ wv, const float* __restrict__ ff1_w,
    const float* __restrict__ ff2_w, const float* __restrict__ w_fuse)
{
    int i = blockIdx.x*256 + threadIdx.x;
    if (i < 12800) {
        int k = i / 200, n = i % 200;
        float v = 0.f;
        if (n < 64)       v = tf32r(wq[k*64 + n]);
        else if (n < 128) v = tf32r(wk[k*64 + n - 64]);
        else if (n < 192) v = tf32r(wv[k*64 + n - 128]);
        g_wqkv[i] = v;
        return;
    }
    i -= 12800;
    if (i < 9216) {
        int P = i / 4608, r = i % 4608, k = r / 72, n = r % 72;
        g_ff1h[i] = (n < 64) ? tf32r(ff1_w[k*128 + P*64 + n]) : 0.f;
        return;
    }
    i -= 9216;
    if (i < 9216) {
        int Kp = i / 4608, r = i % 4608, k = r / 72, n = r % 72;
        g_ff2h[i] = (n < 64) ? tf32r(ff2_w[(Kp*64 + k)*64 + n]) : 0.f;
        return;
    }
    i -= 9216;
    if (i < 4608) {
        int k = i / 72, n = i % 72;
        g_wfuse72[i] = (n < 64) ? tf32r(w_fuse[k*64 + n]) : 0.f;
    }
}

// ---------------------------------------------------------------------------
// Kernel A: q,k,v = x @ [wq|wk|wv] via tf32 mma. 64 pixels/block, 8 warps.
// ws [64][200] (pure float4 copy), xs [64][68]
// ---------------------------------------------------------------------------
__global__ void __launch_bounds__(256,2) qkv_kernel(const float* __restrict__ x)
{
    extern __shared__ float sm[];
    float* ws = sm;            // [64][200]
    float* xs = sm + 12800;    // [64][68]
    const int tid = threadIdx.x;

    {
        const float4* src = (const float4*)g_wqkv;
        float4* dst = (float4*)ws;
        for (int i = tid; i < 3200; i += 256) dst[i] = src[i];
    }
    const int pix0 = blockIdx.x * 64;
    const float4* xg = (const float4*)(x + pix0*64);
    for (int i = tid; i < 1024; i += 256) {
        int m = i >> 4, c4 = i & 15;
        float4 v = xg[i];
        v.x = tf32r(v.x); v.y = tf32r(v.y); v.z = tf32r(v.z); v.w = tf32r(v.w);
        *(float4*)&xs[m*68 + c4*4] = v;
    }
    __syncthreads();

    const int wid = tid >> 5, lane = tid & 31;
    const int gr = lane >> 2, tg = lane & 3;
    const int m0 = (wid >> 1) * 16;
    const int nb = (wid & 1) * 96;
    const unsigned* xs32 = (const unsigned*)xs;
    const unsigned* ws32 = (const unsigned*)ws;

    float d[12][4];
    #pragma unroll
    for (int j = 0; j < 12; j++)
        #pragma unroll
        for (int c = 0; c < 4; c++) d[j][c] = 0.f;

    #pragma unroll
    for (int k0 = 0; k0 < 64; k0 += 8) {
        unsigned a0 = xs32[(m0+gr)*68   + k0+tg];
        unsigned a1 = xs32[(m0+gr+8)*68 + k0+tg];
        unsigned a2 = xs32[(m0+gr)*68   + k0+tg+4];
        unsigned a3 = xs32[(m0+gr+8)*68 + k0+tg+4];
        #pragma unroll
        for (int j = 0; j < 12; j++) {
            int n0 = nb + j*8;
            unsigned b0 = ws32[(k0+tg)*200   + n0+gr];
            unsigned b1 = ws32[(k0+tg+4)*200 + n0+gr];
            mma_tf32(d[j], a0, a1, a2, a3, b0, b1);
        }
    }

    #pragma unroll
    for (int j = 0; j < 12; j++) {
        int n = nb + j*8 + 2*tg;
        float* dst; int nn;
        if (n < 64)       { dst = g_q; nn = n; }
        else if (n < 128) { dst = g_k; nn = n - 64; }
        else              { dst = g_v; nn = n - 128; }
        int m = pix0 + m0 + gr;
        *(float2*)&dst[m*64 + nn]     = make_float2(d[j][0], d[j][1]);
        *(float2*)&dst[(m+8)*64 + nn] = make_float2(d[j][2], d[j][3]);
    }
}

// ---------------------------------------------------------------------------
// Kernel B: fused 3x3 attention + LN1 + FFN + LN2 + fuse conv + BN + relu
// smem (floats):
//   region1 [0,13464): halo [198][68]  |  s_w [64][72]=4608 + s_h [64][132]=8448
//   region2 [13464,17816): s_o [64][68]
//   s_m     [17816,18392)
// ---------------------------------------------------------------------------
#define R2OFF 13464
#define MOFF  17816
#define SMB_FLOATS 18392

__global__ void __launch_bounds__(256,3) attn_ffn_kernel(
    const float* __restrict__ x,
    const float* __restrict__ ln1_g, const float* __restrict__ ln1_b,
    const float* __restrict__ ff1_b,
    const float* __restrict__ ff2_b,
    const float* __restrict__ ln2_g, const float* __restrict__ ln2_b,
    const float* __restrict__ bn_g, const float* __restrict__ bn_b,
    const float* __restrict__ bn_mean, const float* __restrict__ bn_var,
    float* __restrict__ out)
{
    extern __shared__ float sm[];
    float* s_halo = sm;               // [198][68]
    float* s_w    = sm;               // [64][72]  (aliases halo)
    float* s_h    = sm + 4608;        // [64][132]
    float* s_o    = sm + R2OFF;       // [64][68]
    float* s_m    = sm + MOFF;

    const int tid = threadIdx.x;
    if (tid < 64) {
        s_m[tid]        = ln1_g[tid];
        s_m[64 + tid]   = ln1_b[tid];
        s_m[128 + tid]  = ln2_g[tid];
        s_m[192 + tid]  = ln2_b[tid];
        s_m[384 + tid]  = ff2_b[tid];
        float sc = bn_g[tid] * rsqrtf(bn_var[tid] + 1e-3f);
        s_m[448 + tid]  = sc;
        s_m[512 + tid]  = bn_b[tid] - bn_mean[tid]*sc;
    } else if (tid < 192) {
        s_m[256 + (tid - 64)] = ff1_b[tid - 64];
    }

    const int b  = blockIdx.z;
    const int yy = blockIdx.y;
    const int c0 = blockIdx.x * 64;

    // ---- stage k halo: per-row loops, no division ----
    #pragma unroll
    for (int r = 0; r < 3; r++) {
        const int gy = yy + r - 1;
        const bool rowok = (unsigned)gy < HDIM;
        const float* src = g_k + (((long)b*HDIM + gy)*WDIM + c0 - 1)*64;
        for (int idx = tid; idx < 1056; idx += 256) {
            int j = idx >> 4, c4 = idx & 15;
            int gx = c0 + j - 1;
            float4 v = make_float4(0.f, 0.f, 0.f, 0.f);
            if (rowok && (unsigned)gx < WDIM)
                v = *(const float4*)(src + j*64 + c4*4);
            *(float4*)&s_halo[(r*66 + j)*68 + c4*4] = v;
        }
    }

    // ---- q direct from gmem (coalesced), overlaps halo staging ----
    const int p  = tid >> 2;
    const int hd = tid & 3;
    const int base = ((b*HDIM + yy)*WDIM + c0 + p)*64;
    float q[16];
    {
        const float* qp = g_q + base + hd*16;
        #pragma unroll
        for (int i = 0; i < 4; i++)
            *(float4*)&q[4*i] = *(const float4*)(qp + 4*i);
    }
    __syncthreads();

    // ---- attention scores (fp32) ----
    float sc9[9];
    #pragma unroll
    for (int o = 0; o < 9; o++) {
        const int r = o / 3, dxo = o % 3;
        const float* kp = &s_halo[(r*66 + p + dxo)*68 + hd*16];
        float s = 0.f;
        #pragma unroll
        for (int i = 0; i < 4; i++) {
            float4 kk = *(const float4*)&kp[4*i];
            s = fmaf(q[4*i+0], kk.x, s);
            s = fmaf(q[4*i+1], kk.y, s);
            s = fmaf(q[4*i+2], kk.z, s);
            s = fmaf(q[4*i+3], kk.w, s);
        }
        sc9[o] = s * 0.25f;
    }
    float mx = sc9[0];
    #pragma unroll
    for (int o = 1; o < 9; o++) mx = fmaxf(mx, sc9[o]);
    float ssum = 0.f;
    #pragma unroll
    for (int o = 0; o < 9; o++) { sc9[o] = __expf(sc9[o] - mx); ssum += sc9[o]; }
    const float sinv = 1.f / ssum;

    float xr[16];
    #pragma unroll
    for (int i = 0; i < 4; i++)
        *(float4*)&xr[4*i] = *(const float4*)(x + base + hd*16 + 4*i);

    __syncthreads();
    // ---- stage v halo ----
    #pragma unroll
    for (int r = 0; r < 3; r++) {
        const int gy = yy + r - 1;
        const bool rowok = (unsigned)gy < HDIM;
        const float* src = g_v + (((long)b*HDIM + gy)*WDIM + c0 - 1)*64;
        for (int idx = tid; idx < 1056; idx += 256) {
            int j = idx >> 4, c4 = idx & 15;
            int gx = c0 + j - 1;
            float4 v = make_float4(0.f, 0.f, 0.f, 0.f);
            if (rowok && (unsigned)gx < WDIM)
                v = *(const float4*)(src + j*64 + c4*4);
            *(float4*)&s_halo[(r*66 + j)*68 + c4*4] = v;
        }
    }
    __syncthreads();

    // ---- weighted sum of v ----
    float acc[16];
    #pragma unroll
    for (int d = 0; d < 16; d++) acc[d] = 0.f;
    #pragma unroll
    for (int o = 0; o < 9; o++) {
        const int r = o / 3, dxo = o % 3;
        const float w = sc9[o] * sinv;
        const float* vp = &s_halo[(r*66 + p + dxo)*68 + hd*16];
        #pragma unroll
        for (int i = 0; i < 4; i++) {
            float4 vv = *(const float4*)&vp[4*i];
            acc[4*i+0] = fmaf(w, vv.x, acc[4*i+0]);
            acc[4*i+1] = fmaf(w, vv.y, acc[4*i+1]);
            acc[4*i+2] = fmaf(w, vv.z, acc[4*i+2]);
            acc[4*i+3] = fmaf(w, vv.w, acc[4*i+3]);
        }
    }

    // ---- LN1 with residual; store tf32-rounded (A of GEMM1) ----
    {
        float s1 = 0.f, s2 = 0.f;
        #pragma unroll
        for (int d = 0; d < 16; d++) {
            acc[d] += xr[d];
            s1 += acc[d];
            s2 = fmaf(acc[d], acc[d], s2);
        }
        s1 += __shfl_xor_sync(0xffffffff, s1, 1);
        s2 += __shfl_xor_sync(0xffffffff, s2, 1);
        s1 += __shfl_xor_sync(0xffffffff, s1, 2);
        s2 += __shfl_xor_sync(0xffffffff, s2, 2);
        const float mean = s1 * (1.f/64.f);
        const float var  = s2 * (1.f/64.f) - mean*mean;
        const float rstd = rsqrtf(var + 1e-3f);
        #pragma unroll
        for (int i = 0; i < 4; i++) {
            const int c = hd*16 + 4*i;
            float4 w4;
            w4.x = tf32r((acc[4*i+0] - mean)*rstd*s_m[c+0] + s_m[64+c+0]);
            w4.y = tf32r((acc[4*i+1] - mean)*rstd*s_m[c+1] + s_m[64+c+1]);
            w4.z = tf32r((acc[4*i+2] - mean)*rstd*s_m[c+2] + s_m[64+c+2]);
            w4.w = tf32r((acc[4*i+3] - mean)*rstd*s_m[c+3] + s_m[64+c+3]);
            *(float4*)&s_o[p*68 + c] = w4;
        }
    }
    __syncthreads();   // halo reads done; LN1 visible

    const int wid = tid >> 5, lane = tid & 31;
    const int gr = lane >> 2, tg = lane & 3;
    const int m0 = (wid >> 1) * 16;
    const int wn = wid & 1;
    const unsigned* so32 = (const unsigned*)s_o;
    const unsigned* sh32 = (const unsigned*)s_h;
    const unsigned* sw32 = (const unsigned*)s_w;

    // ---- GEMM1: h = relu(o @ ff1 + b1), two n-halves ----
    #pragma unroll
    for (int P = 0; P < 2; P++) {
        {
            const float4* src = (const float4*)(g_ff1h + P*4608);
            float4* dst = (float4*)s_w;
            for (int i = tid; i < 1152; i += 256) dst[i] = src[i];
        }
        __syncthreads();
        float d1[4][4];
        #pragma unroll
        for (int j = 0; j < 4; j++)
            #pragma unroll
            for (int c = 0; c < 4; c++) d1[j][c] = 0.f;
        #pragma unroll
        for (int k0 = 0; k0 < 64; k0 += 8) {
            unsigned a0 = so32[(m0+gr)*68   + k0+tg];
            unsigned a1 = so32[(m0+gr+8)*68 + k0+tg];
            unsigned a2 = so32[(m0+gr)*68   + k0+tg+4];
            unsigned a3 = so32[(m0+gr+8)*68 + k0+tg+4];
            #pragma unroll
            for (int j = 0; j < 4; j++) {
                int n0 = wn*32 + j*8;
                unsigned b0 = sw32[(k0+tg)*72   + n0+gr];
                unsigned b1 = sw32[(k0+tg+4)*72 + n0+gr];
                mma_tf32(d1[j], a0, a1, a2, a3, b0, b1);
            }
        }
        #pragma unroll
        for (int j = 0; j < 4; j++) {
            int n = P*64 + wn*32 + j*8 + 2*tg;
            float bb0 = s_m[256 + n], bb1 = s_m[256 + n + 1];
            *(float2*)&s_h[(m0+gr)*132 + n] = make_float2(
                tf32r(fmaxf(d1[j][0] + bb0, 0.f)), tf32r(fmaxf(d1[j][1] + bb1, 0.f)));
            *(float2*)&s_h[(m0+gr+8)*132 + n] = make_float2(
                tf32r(fmaxf(d1[j][2] + bb0, 0.f)), tf32r(fmaxf(d1[j][3] + bb1, 0.f)));
        }
        __syncthreads();
    }

    // ---- GEMM2: o += h @ ff2 + b2, two k-halves ----
    float d2[4][4];
    #pragma unroll
    for (int j = 0; j < 4; j++)
        #pragma unroll
        for (int c = 0; c < 4; c++) d2[j][c] = 0.f;
    #pragma unroll
    for (int Kp = 0; Kp < 2; Kp++) {
        {
            const float4* src = (const float4*)(g_ff2h + Kp*4608);
            float4* dst = (float4*)s_w;
            for (int i = tid; i < 1152; i += 256) dst[i] = src[i];
        }
        __syncthreads();
        #pragma unroll
        for (int k0 = 0; k0 < 64; k0 += 8) {
            int kc = Kp*64 + k0;
            unsigned a0 = sh32[(m0+gr)*132   + kc+tg];
            unsigned a1 = sh32[(m0+gr+8)*132 + kc+tg];
            unsigned a2 = sh32[(m0+gr)*132   + kc+tg+4];
            unsigned a3 = sh32[(m0+gr+8)*132 + kc+tg+4];
            #pragma unroll
            for (int j = 0; j < 4; j++) {
                int n0 = wn*32 + j*8;
                unsigned b0 = sw32[(k0+tg)*72   + n0+gr];
                unsigned b1 = sw32[(k0+tg+4)*72 + n0+gr];
                mma_tf32(d2[j], a0, a1, a2, a3, b0, b1);
            }
        }
        __syncthreads();
    }
    #pragma unroll
    for (int j = 0; j < 4; j++) {
        int n = wn*32 + j*8 + 2*tg;
        float bb0 = s_m[384 + n], bb1 = s_m[384 + n + 1];
        float2 o0 = *(float2*)&s_o[(m0+gr)*68 + n];
        float2 o1 = *(float2*)&s_o[(m0+gr+8)*68 + n];
        *(float2*)&s_o[(m0+gr)*68 + n]   = make_float2(o0.x + d2[j][0] + bb0, o0.y + d2[j][1] + bb1);
        *(float2*)&s_o[(m0+gr+8)*68 + n] = make_float2(o1.x + d2[j][2] + bb0, o1.y + d2[j][3] + bb1);
    }
    __syncthreads();

    // ---- LN2; store tf32-rounded (A of GEMM3) ----
    {
        float v2[16], s1 = 0.f, s2 = 0.f;
        #pragma unroll
        for (int i = 0; i < 4; i++) {
            float4 t = *(const float4*)&s_o[p*68 + hd*16 + 4*i];
            v2[4*i+0] = t.x; v2[4*i+1] = t.y; v2[4*i+2] = t.z; v2[4*i+3] = t.w;
        }
        #pragma unroll
        for (int d = 0; d < 16; d++) { s1 += v2[d]; s2 = fmaf(v2[d], v2[d], s2); }
        s1 += __shfl_xor_sync(0xffffffff, s1, 1);
        s2 += __shfl_xor_sync(0xffffffff, s2, 1);
        s1 += __shfl_xor_sync(0xffffffff, s1, 2);
        s2 += __shfl_xor_sync(0xffffffff, s2, 2);
        const float mean = s1 * (1.f/64.f);
        const float var  = s2 * (1.f/64.f) - mean*mean;
        const float rstd = rsqrtf(var + 1e-3f);
        #pragma unroll
        for (int i = 0; i < 4; i++) {
            const int c = hd*16 + 4*i;
            float4 w4;
            w4.x = tf32r((v2[4*i+0] - mean)*rstd*s_m[128+c+0] + s_m[192+c+0]);
            w4.y = tf32r((v2[4*i+1] - mean)*rstd*s_m[128+c+1] + s_m[192+c+1]);
            w4.z = tf32r((v2[4*i+2] - mean)*rstd*s_m[128+c+2] + s_m[192+c+2]);
            w4.w = tf32r((v2[4*i+3] - mean)*rstd*s_m[128+c+3] + s_m[192+c+3]);
            *(float4*)&s_o[p*68 + c] = w4;
        }
    }
    // stage fuse weights
    {
        const float4* src = (const float4*)g_wfuse72;
        float4* dst = (float4*)s_w;
        for (int i = tid; i < 1152; i += 256) dst[i] = src[i];
    }
    __syncthreads();

    // ---- GEMM3: fuse conv + BN + relu, direct global store ----
    {
        float d3[4][4];
        #pragma unroll
        for (int j = 0; j < 4; j++)
            #pragma unroll
            for (int c = 0; c < 4; c++) d3[j][c] = 0.f;
        #pragma unroll
        for (int k0 = 0; k0 < 64; k0 += 8) {
            unsigned a0 = so32[(m0+gr)*68   + k0+tg];
            unsigned a1 = so32[(m0+gr+8)*68 + k0+tg];
            unsigned a2 = so32[(m0+gr)*68   + k0+tg+4];
            unsigned a3 = so32[(m0+gr+8)*68 + k0+tg+4];
            #pragma unroll
            for (int j = 0; j < 4; j++) {
                int n0 = wn*32 + j*8;
                unsigned b0 = sw32[(k0+tg)*72   + n0+gr];
                unsigned b1 = sw32[(k0+tg+4)*72 + n0+gr];
                mma_tf32(d3[j], a0, a1, a2, a3, b0, b1);
            }
        }
        float* ob = out + ((b*HDIM + yy)*WDIM + c0)*64;
        #pragma unroll
        for (int j = 0; j < 4; j++) {
            int n = wn*32 + j*8 + 2*tg;
            float sc0 = s_m[448 + n], sc1 = s_m[448 + n + 1];
            float sh0 = s_m[512 + n], sh1 = s_m[512 + n + 1];
            *(float2*)&ob[(m0+gr)*64 + n] = make_float2(
                fmaxf(d3[j][0]*sc0 + sh0, 0.f), fmaxf(d3[j][1]*sc1 + sh1, 0.f));
            *(float2*)&ob[(m0+gr+8)*64 + n] = make_float2(
                fmaxf(d3[j][2]*sc0 + sh0, 0.f), fmaxf(d3[j][3]*sc1 + sh1, 0.f));
        }
    }
}

extern "C" void kernel_launch(void* const* d_in, const int* in_sizes, int n_in,
                              void* d_out, int out_size)
{
    const float* x      = (const float*)d_in[0];
    const float* wq     = (const float*)d_in[1];
    const float* wk     = (const float*)d_in[2];
    const float* wv     = (const float*)d_in[3];
    const float* ln1_g  = (const float*)d_in[4];
    const float* ln1_b  = (const float*)d_in[5];
    const float* ff1_w  = (const float*)d_in[6];
    const float* ff1_b  = (const float*)d_in[7];
    const float* ff2_w  = (const float*)d_in[8];
    const float* ff2_b  = (const float*)d_in[9];
    const float* ln2_g  = (const float*)d_in[10];
    const float* ln2_b  = (const float*)d_in[11];
    const float* w_fuse = (const float*)d_in[12];
    const float* bn_g   = (const float*)d_in[13];
    const float* bn_b   = (const float*)d_in[14];
    const float* bn_mean= (const float*)d_in[15];
    const float* bn_var = (const float*)d_in[16];
    float* out = (float*)d_out;

    const int SMEM_A = (12800 + 64*68) * 4;   // 68608 B
    const int SMEM_B = SMB_FLOATS * 4;        // 73568 B
    cudaFuncSetAttribute(qkv_kernel, cudaFuncAttributeMaxDynamicSharedMemorySize, SMEM_A);
    cudaFuncSetAttribute(attn_ffn_kernel, cudaFuncAttributeMaxDynamicSharedMemorySize, SMEM_B);

    cvt_weights_kernel<<<140, 256>>>(wq, wk, wv, ff1_w, ff2_w, w_fuse);
    qkv_kernel<<<NPIX/64, 256, SMEM_A>>>(x);

    dim3 grid(WDIM/64, HDIM, BATCH);
    attn_ffn_kernel<<<grid, 256, SMEM_B>>>(
        x, ln1_g, ln1_b, ff1_b, ff2_b,
        ln2_g, ln2_b, bn_g, bn_b, bn_mean, bn_var, out);
}